// round 12
// baseline (speedup 1.0000x reference)
#include <cuda_runtime.h>

#define Hdim 64
#define Nn   100000
#define Ee   1000000
#define Gg   64

typedef unsigned long long u64;

#define SWZ(k) ((((k) >> 4) & 3) << 3)

// ---------------- scratch (static device arrays: no allocation) ----------------
__device__ float g_aggsum[Nn * Hdim];
__device__ float g_aggcnt[Nn];
__device__ float g_gsum[Gg * Hdim];
__device__ float g_gcnt[Gg];
__device__ float g_PUe[Gg * Hdim];    // u @ eW1d
__device__ float g_PUn2[Gg * Hdim];   // u @ n2W1b + n2b1
__device__ float g_P1p[Nn * Hdim];    // x @ eW1a + PUe[batch] + eb1
__device__ float g_P2Q[Nn * 2 * Hdim];// [x @ eW1b | x @ nW1a + nb1]

// ---------------- packed f32x2 helpers ----------------
__device__ __forceinline__ u64 bcast2(float x) {
    u64 r; unsigned xi = __float_as_uint(x);
    asm("mov.b64 %0, {%1, %2};" : "=l"(r) : "r"(xi), "r"(xi));
    return r;
}
__device__ __forceinline__ void ffma2(u64& d, u64 a, u64 b) {
    asm("fma.rn.f32x2 %0, %1, %2, %0;" : "+l"(d) : "l"(a), "l"(b));
}
__device__ __forceinline__ float2 unpack2(u64 v) {
    unsigned lo, hi;
    asm("mov.b64 {%0, %1}, %2;" : "=r"(lo), "=r"(hi) : "l"(v));
    return make_float2(__uint_as_float(lo), __uint_as_float(hi));
}
__device__ __forceinline__ float fsel(float4 v, int i) {
    return i == 0 ? v.x : (i == 1 ? v.y : (i == 2 ? v.z : v.w));
}

__device__ __forceinline__ float gelu_f(float v) {
    return 0.5f * v * (1.0f + erff(v * 0.7071067811865476f));
}

__device__ __forceinline__ void zero8(u64 (&a)[4][2]) {
#pragma unroll
    for (int i = 0; i < 4; ++i) { a[i][0] = 0ULL; a[i][1] = 0ULL; }
}

template <int NT>
__device__ __forceinline__ void cp_smem(float* dst, const float* src, int nfloats, int tid) {
    const float4* s4 = (const float4*)src;
    float4* d4 = (float4*)dst;
    for (int i = tid; i < (nfloats >> 2); i += NT) d4[i] = s4[i];
}

// type-A GEMM (4i x 4j packed): X k-major in smem, stride 68, e-index XOR-swizzled by SWZ(k)
template <int K, int KB>
__device__ __forceinline__ void gemmA2(const float* __restrict__ Xs, const float* __restrict__ Ws,
                                       int i4, int j4, u64 (&a)[4][2]) {
#pragma unroll 4
    for (int k = 0; k < K; ++k) {
        int kk = KB + k;
        float4 xv = *(const float4*)(Xs + kk * 68 + (i4 ^ SWZ(kk)));
        ulonglong2 wv = *(const ulonglong2*)(Ws + k * 64 + j4);
        u64 x0 = bcast2(xv.x), x1 = bcast2(xv.y), x2 = bcast2(xv.z), x3 = bcast2(xv.w);
        ffma2(a[0][0], x0, wv.x); ffma2(a[0][1], x0, wv.y);
        ffma2(a[1][0], x1, wv.x); ffma2(a[1][1], x1, wv.y);
        ffma2(a[2][0], x2, wv.x); ffma2(a[2][1], x2, wv.y);
        ffma2(a[3][0], x3, wv.x); ffma2(a[3][1], x3, wv.y);
    }
}

// type-B GEMM (4i x 4j packed): H row-major in smem (stride 68), float4 loads along k
template <int K>
__device__ __forceinline__ void gemmB2(const float* __restrict__ Hs, const float* __restrict__ Ws,
                                       int i4, int j4, u64 (&a)[4][2]) {
#pragma unroll 2
    for (int k0 = 0; k0 < K; k0 += 4) {
        float4 h0 = *(const float4*)(Hs + (i4 + 0) * 68 + k0);
        float4 h1 = *(const float4*)(Hs + (i4 + 1) * 68 + k0);
        float4 h2 = *(const float4*)(Hs + (i4 + 2) * 68 + k0);
        float4 h3 = *(const float4*)(Hs + (i4 + 3) * 68 + k0);
#pragma unroll
        for (int dk = 0; dk < 4; ++dk) {
            ulonglong2 wv = *(const ulonglong2*)(Ws + (k0 + dk) * 64 + j4);
            u64 x0 = bcast2(fsel(h0, dk));
            u64 x1 = bcast2(fsel(h1, dk));
            u64 x2 = bcast2(fsel(h2, dk));
            u64 x3 = bcast2(fsel(h3, dk));
            ffma2(a[0][0], x0, wv.x); ffma2(a[0][1], x0, wv.y);
            ffma2(a[1][0], x1, wv.x); ffma2(a[1][1], x1, wv.y);
            ffma2(a[2][0], x2, wv.x); ffma2(a[2][1], x2, wv.y);
            ffma2(a[3][0], x3, wv.x); ffma2(a[3][1], x3, wv.y);
        }
    }
}

// bias(broadcast) + GELU -> H row-major
__device__ __forceinline__ void storeH2(float* __restrict__ Hs, int i4, int j4,
                                        u64 (&a)[4][2], const float* __restrict__ bias) {
    float4 b = *(const float4*)(bias + j4);
#pragma unroll
    for (int r = 0; r < 4; ++r) {
        float2 p0 = unpack2(a[r][0]);
        float2 p1 = unpack2(a[r][1]);
        float* row = Hs + (i4 + r) * 68 + j4;
        row[0] = gelu_f(p0.x + b.x);
        row[1] = gelu_f(p0.y + b.y);
        row[2] = gelu_f(p1.x + b.z);
        row[3] = gelu_f(p1.y + b.w);
    }
}

// per-row offset(register) + GELU -> H row-major
__device__ __forceinline__ void storeH2off(float* __restrict__ Hs, int i4, int j4,
                                           u64 (&a)[4][2], const float4* __restrict__ off) {
#pragma unroll
    for (int r = 0; r < 4; ++r) {
        float2 p0 = unpack2(a[r][0]);
        float2 p1 = unpack2(a[r][1]);
        float* row = Hs + (i4 + r) * 68 + j4;
        row[0] = gelu_f(p0.x + off[r].x);
        row[1] = gelu_f(p0.y + off[r].y);
        row[2] = gelu_f(p1.x + off[r].z);
        row[3] = gelu_f(p1.y + off[r].w);
    }
}

// per-row LayerNorm stats over 64 cols of row-major H
__device__ __forceinline__ void ln_stats(const float* __restrict__ Hs, float* __restrict__ st, int tid) {
    if (tid < 64) {
        float s = 0.0f, s2 = 0.0f;
#pragma unroll
        for (int c = 0; c < 16; ++c) {
            float4 v = *(const float4*)(Hs + tid * 68 + 4 * c);
            s += v.x + v.y + v.z + v.w;
            s2 += v.x * v.x + v.y * v.y + v.z * v.z + v.w * v.w;
        }
        float m = s * (1.0f / 64.0f);
        float var = s2 * (1.0f / 64.0f) - m * m;
        st[tid] = m;
        st[64 + tid] = rsqrtf(fmaxf(var, 0.0f) + 1e-5f);
    }
}

__device__ __forceinline__ void red_v4(float* p, float4 v) {
    asm volatile("red.global.add.v4.f32 [%0], {%1,%2,%3,%4};"
                 :: "l"(p), "f"(v.x), "f"(v.y), "f"(v.z), "f"(v.w) : "memory");
}

// ---------------- zero scratch ----------------
__global__ void zero_kernel() {
    int total = Nn * Hdim + Nn + Gg * Hdim + Gg;
    for (int i = blockIdx.x * blockDim.x + threadIdx.x; i < total; i += gridDim.x * blockDim.x) {
        if (i < Nn * Hdim) g_aggsum[i] = 0.0f;
        else if (i < Nn * Hdim + Nn) g_aggcnt[i - Nn * Hdim] = 0.0f;
        else if (i < Nn * Hdim + Nn + Gg * Hdim) g_gsum[i - Nn * Hdim - Nn] = 0.0f;
        else g_gcnt[i - Nn * Hdim - Nn - Gg * Hdim] = 0.0f;
    }
}

// ---------------- P0: per-graph precompute PUe = u@eW1d, PUn2 = u@n2W1b + n2b1 ----------------
__global__ __launch_bounds__(256, 1) void pu_kernel(
    const float* __restrict__ u, const float* __restrict__ eW1,
    const float* __restrict__ n2W1, const float* __restrict__ n2b1) {
    __shared__ float su[4096], sw1[4096], sw2[4096];
    int tid = threadIdx.x;
    cp_smem<256>(su, u, 4096, tid);
    cp_smem<256>(sw1, eW1 + 192 * 64, 4096, tid);   // eW1d
    cp_smem<256>(sw2, n2W1 + 64 * 64, 4096, tid);   // n2W1b
    __syncthreads();
    int g = tid >> 2, q = tid & 3;
#pragma unroll 4
    for (int jj = 0; jj < 16; ++jj) {
        int j = q * 16 + jj;
        float s1 = 0.0f, s2 = 0.0f;
#pragma unroll 4
        for (int k = 0; k < 64; ++k) {
            float uv = su[g * 64 + k];
            s1 += uv * sw1[k * 64 + j];
            s2 += uv * sw2[k * 64 + j];
        }
        g_PUe[g * 64 + j] = s1;
        g_PUn2[g * 64 + j] = s2 + n2b1[j];
    }
}

// ---------------- P1: per-node precompute P1p, P2, Q ----------------
#define P_OWA 0
#define P_OWB 4096
#define P_OWQ 8192
#define P_OBp 12288
#define P_OX  12416
#define P_SBT 16768
#define P_SMEM_BYTES (16832 * 4)

__global__ __launch_bounds__(256, 2) void node_pre_kernel(
    const float* __restrict__ x, const int* __restrict__ batch,
    const float* __restrict__ eW1, const float* __restrict__ eb1,
    const float* __restrict__ nW1, const float* __restrict__ nb1) {
    extern __shared__ float sm[];
    int tid = threadIdx.x;
    cp_smem<256>(sm + P_OWA, eW1, 4096, tid);            // eW1a (rows 0..63)
    cp_smem<256>(sm + P_OWB, eW1 + 4096, 4096, tid);     // eW1b (rows 64..127)
    cp_smem<256>(sm + P_OWQ, nW1, 4096, tid);            // nW1a (rows 0..63)
    if (tid < 64) { sm[P_OBp + tid] = eb1[tid]; sm[P_OBp + 64 + tid] = nb1[tid]; }
    __syncthreads();

    const int i4 = (tid >> 4) << 2;
    const int j4 = (tid & 15) << 2;
    int* sbt = (int*)(sm + P_SBT);
    int t = blockIdx.x;

    // gather x tile k-major
    {
        int e = tid >> 2, q = tid & 3;
        int n = t * 64 + e;
        bool valid = n < Nn;
        if (q == 0) sbt[e] = valid ? batch[n] : 0;
#pragma unroll
        for (int tt = 0; tt < 4; ++tt) {
            int k0 = q * 16 + tt * 4;
            float4 v = make_float4(0.f, 0.f, 0.f, 0.f);
            if (valid) v = ((const float4*)(x + (size_t)n * 64))[k0 >> 2];
            float* d = sm + P_OX + k0 * 68 + (e ^ SWZ(k0));
            d[0] = v.x; d[68] = v.y; d[136] = v.z; d[204] = v.w;
        }
    }
    __syncthreads();

    u64 acc[4][2];
    // P1p = x@W1a + PUe[batch] + eb1  (pre-activation, no gelu)
    zero8(acc);
    gemmA2<64, 0>(sm + P_OX, sm + P_OWA, i4, j4, acc);
#pragma unroll
    for (int r = 0; r < 4; ++r) {
        int n2 = t * 64 + i4 + r;
        if (n2 < Nn) {
            int b = sbt[i4 + r];
            float4 pu = *(const float4*)(g_PUe + b * 64 + j4);
            float4 b1 = *(const float4*)(sm + P_OBp + j4);
            float2 p0 = unpack2(acc[r][0]);
            float2 p1 = unpack2(acc[r][1]);
            float4 o = make_float4(p0.x + pu.x + b1.x, p0.y + pu.y + b1.y,
                                   p1.x + pu.z + b1.z, p1.y + pu.w + b1.w);
            *(float4*)(g_P1p + (size_t)n2 * 64 + j4) = o;
        }
    }
    // P2 = x@W1b
    zero8(acc);
    gemmA2<64, 0>(sm + P_OX, sm + P_OWB, i4, j4, acc);
#pragma unroll
    for (int r = 0; r < 4; ++r) {
        int n2 = t * 64 + i4 + r;
        if (n2 < Nn) {
            float2 p0 = unpack2(acc[r][0]);
            float2 p1 = unpack2(acc[r][1]);
            *(float4*)(g_P2Q + (size_t)n2 * 128 + j4) = make_float4(p0.x, p0.y, p1.x, p1.y);
        }
    }
    // Q = x@nW1a + nb1
    zero8(acc);
    gemmA2<64, 0>(sm + P_OX, sm + P_OWQ, i4, j4, acc);
#pragma unroll
    for (int r = 0; r < 4; ++r) {
        int n2 = t * 64 + i4 + r;
        if (n2 < Nn) {
            float4 b1 = *(const float4*)(sm + P_OBp + 64 + j4);
            float2 p0 = unpack2(acc[r][0]);
            float2 p1 = unpack2(acc[r][1]);
            *(float4*)(g_P2Q + (size_t)n2 * 128 + 64 + j4) =
                make_float4(p0.x + b1.x, p0.y + b1.y, p1.x + b1.z, p1.y + b1.w);
        }
    }
}

// ---------------- kernel 1: fused edge+message MLPs (decomposed, 256 thr, 2 CTA/SM) ----------------
#define E_OW1C 0
#define E_OW2  4096
#define E_ONB  8192
#define E_ON2  12288
#define E_OBS  16384
#define E_OK   16768
#define E_OH   21120
#define E_OST  25472
#define E_OIDX 25600
#define E_SMEM_BYTES (25728 * 4)

__global__ __launch_bounds__(256, 2) void edge_node1_kernel(
    const int* __restrict__ ei, const float* __restrict__ ea,
    const float* __restrict__ eW1, const float* __restrict__ eb2v,
    const float* __restrict__ eW2, const float* __restrict__ egm,
    const float* __restrict__ ebt,
    const float* __restrict__ nW1, const float* __restrict__ nW2,
    const float* __restrict__ nb2v, const float* __restrict__ ngm,
    const float* __restrict__ nbt,
    float* __restrict__ edge_out) {
    extern __shared__ float sm[];
    int tid = threadIdx.x;
    cp_smem<256>(sm + E_OW1C, eW1 + 8192, 4096, tid);   // eW1c (rows 128..191)
    cp_smem<256>(sm + E_OW2, eW2, 4096, tid);
    cp_smem<256>(sm + E_ONB, nW1 + 4096, 4096, tid);    // nW1b (rows 64..127)
    cp_smem<256>(sm + E_ON2, nW2, 4096, tid);
    if (tid < 64) {
        sm[E_OBS + tid] = eb2v[tid];        sm[E_OBS + 64 + tid] = egm[tid];
        sm[E_OBS + 128 + tid] = ebt[tid];   sm[E_OBS + 192 + tid] = nb2v[tid];
        sm[E_OBS + 256 + tid] = ngm[tid];   sm[E_OBS + 320 + tid] = nbt[tid];
    }
    __syncthreads();

    const int i4 = (tid >> 4) << 2;
    const int j4 = (tid & 15) << 2;
    int* sidx = (int*)(sm + E_OIDX);

    for (int t = blockIdx.x; t < Ee / 64; t += gridDim.x) {
        // indices + aggcnt
        if (tid < 64) {
            int eg_ = t * 64 + tid;
            int r = ei[eg_], c = ei[Ee + eg_];
            sidx[tid] = r; sidx[64 + tid] = c;
            atomicAdd(&g_aggcnt[r], 1.0f);
        }
        // ea gather -> k-major swizzled
        {
            int e = tid >> 2, q = tid & 3;
            const float4* s4 = (const float4*)(ea + (size_t)(t * 64 + e) * 64);
#pragma unroll
            for (int tt = 0; tt < 4; ++tt) {
                int k0 = q * 16 + tt * 4;
                float4 v = s4[k0 >> 2];
                float* d = sm + E_OK + k0 * 68 + (e ^ SWZ(k0));
                d[0] = v.x; d[68] = v.y; d[136] = v.z; d[204] = v.w;
            }
        }
        __syncthreads();

        // per-row offsets into registers
        float4 off1[4], off2[4];
#pragma unroll
        for (int r = 0; r < 4; ++r) {
            int row = sidx[i4 + r], col = sidx[64 + i4 + r];
            float4 a1 = *(const float4*)(g_P1p + (size_t)row * 64 + j4);
            float4 a2 = *(const float4*)(g_P2Q + (size_t)col * 128 + j4);
            off1[r] = make_float4(a1.x + a2.x, a1.y + a2.y, a1.z + a2.z, a1.w + a2.w);
            off2[r] = *(const float4*)(g_P2Q + (size_t)col * 128 + 64 + j4);
        }

        u64 acc[4][2];
        // edge layer1: ea@W1c + off1 (includes x/u parts + eb1) -> gelu -> H
        zero8(acc);
        gemmA2<64, 0>(sm + E_OK, sm + E_OW1C, i4, j4, acc);
        storeH2off(sm + E_OH, i4, j4, acc, off1);
        __syncthreads();
        // edge layer2
        zero8(acc);
        gemmB2<64>(sm + E_OH, sm + E_OW2, i4, j4, acc);
        __syncthreads();
        storeH2(sm + E_OH, i4, j4, acc, sm + E_OBS + 0);
        __syncthreads();
        ln_stats(sm + E_OH, sm + E_OST, tid);
        __syncthreads();
        // LN -> edge_attr_new: write global + k-major into E_OK (overwrite ea)
        {
            int j = tid & 63, g2 = tid >> 6;
            float gj = sm[E_OBS + 64 + j], bj = sm[E_OBS + 128 + j];
            float* ebase = edge_out + (size_t)t * 64 * 64;
#pragma unroll
            for (int r = 0; r < 16; ++r) {
                int e = g2 * 16 + r;
                float v = sm[E_OH + e * 68 + j];
                float nv = (v - sm[E_OST + e]) * sm[E_OST + 64 + e] * gj + bj;
                sm[E_OK + j * 68 + (e ^ SWZ(j))] = nv;
                ebase[(size_t)e * 64 + j] = nv;
            }
        }
        __syncthreads();
        // message layer1: ean@nW1b + off2 (includes x[col]@nW1a + nb1)
        zero8(acc);
        gemmA2<64, 0>(sm + E_OK, sm + E_ONB, i4, j4, acc);
        storeH2off(sm + E_OH, i4, j4, acc, off2);
        __syncthreads();
        // message layer2
        zero8(acc);
        gemmB2<64>(sm + E_OH, sm + E_ON2, i4, j4, acc);
        __syncthreads();
        storeH2(sm + E_OH, i4, j4, acc, sm + E_OBS + 192);
        __syncthreads();
        ln_stats(sm + E_OH, sm + E_OST, tid);
        __syncthreads();
        // LN + scatter into aggsum[row]
        {
            float4 g4 = *(const float4*)(sm + E_OBS + 256 + j4);
            float4 b4 = *(const float4*)(sm + E_OBS + 320 + j4);
#pragma unroll
            for (int ebk = 0; ebk < 4; ++ebk) {
                int e = (tid >> 4) + (ebk << 4);
                float mn = sm[E_OST + e], rs = sm[E_OST + 64 + e];
                float4 v = *(const float4*)(sm + E_OH + e * 68 + j4);
                v.x = (v.x - mn) * rs * g4.x + b4.x;
                v.y = (v.y - mn) * rs * g4.y + b4.y;
                v.z = (v.z - mn) * rs * g4.z + b4.z;
                v.w = (v.w - mn) * rs * g4.w + b4.w;
                red_v4(g_aggsum + (size_t)sidx[e] * 64 + j4, v);
            }
        }
        __syncthreads();
    }
}

// ---------------- kernel 2: node update (decomposed K=64) ----------------
#define N_OW1 0
#define N_OW2 4096
#define N_OB  8192
#define N_OX  8384
#define N_OH  12736
#define N_OST 17088
#define N_OBI 17216
#define N_SMEM_BYTES (17280 * 4)

__global__ __launch_bounds__(256, 2) void node2_kernel(
    const int* __restrict__ batch,
    const float* __restrict__ W1, const float* __restrict__ W2,
    const float* __restrict__ b2, const float* __restrict__ gm,
    const float* __restrict__ bt,
    float* __restrict__ x_out) {
    extern __shared__ float sm[];
    int tid = threadIdx.x;
    cp_smem<256>(sm + N_OW1, W1, 4096, tid);   // n2W1a (rows 0..63)
    cp_smem<256>(sm + N_OW2, W2, 4096, tid);
    if (tid < 64) {
        sm[N_OB + tid] = b2[tid]; sm[N_OB + 64 + tid] = gm[tid]; sm[N_OB + 128 + tid] = bt[tid];
    }
    __syncthreads();
    const int i4 = (tid >> 4) << 2;
    const int j4 = (tid & 15) << 2;
    int* sbi = (int*)(sm + N_OBI);
    const int nTiles = (Nn + 63) / 64;

    for (int t = blockIdx.x; t < nTiles; t += gridDim.x) {
        {
            int e = tid >> 2, q = tid & 3;
            int n = t * 64 + e;
            bool valid = n < Nn;
            if (q == 0) {
                int b = valid ? batch[n] : 0;
                sbi[e] = b;
                if (valid) atomicAdd(&g_gcnt[b], 1.0f);
            }
            float inv = valid ? 1.0f / fmaxf(g_aggcnt[n], 1.0f) : 1.0f;
#pragma unroll
            for (int tt = 0; tt < 4; ++tt) {
                int k0 = q * 16 + tt * 4;
                float4 v = make_float4(0.f, 0.f, 0.f, 0.f);
                if (valid) {
                    v = ((const float4*)(g_aggsum + (size_t)n * 64))[k0 >> 2];
                    v.x *= inv; v.y *= inv; v.z *= inv; v.w *= inv;
                }
                float* d = sm + N_OX + k0 * 68 + (e ^ SWZ(k0));
                d[0] = v.x; d[68] = v.y; d[136] = v.z; d[204] = v.w;
            }
        }
        __syncthreads();
        // offsets: PUn2[batch[n]] (includes u-part + n2b1)
        float4 off[4];
#pragma unroll
        for (int r = 0; r < 4; ++r) {
            int n2 = t * 64 + i4 + r;
            off[r] = make_float4(0.f, 0.f, 0.f, 0.f);
            if (n2 < Nn) off[r] = *(const float4*)(g_PUn2 + sbi[i4 + r] * 64 + j4);
        }
        u64 acc[4][2];
        zero8(acc);
        gemmA2<64, 0>(sm + N_OX, sm + N_OW1, i4, j4, acc);
        storeH2off(sm + N_OH, i4, j4, acc, off);
        __syncthreads();
        zero8(acc);
        gemmB2<64>(sm + N_OH, sm + N_OW2, i4, j4, acc);
        __syncthreads();
        storeH2(sm + N_OH, i4, j4, acc, sm + N_OB);
        __syncthreads();
        ln_stats(sm + N_OH, sm + N_OST, tid);
        __syncthreads();
        {
            int j = tid & 63, g2 = tid >> 6;
            float gj = sm[N_OB + 64 + j], bj = sm[N_OB + 128 + j];
#pragma unroll
            for (int r = 0; r < 16; ++r) {
                int e = g2 * 16 + r;
                int n = t * 64 + e;
                float v = sm[N_OH + e * 68 + j];
                float nv = (v - sm[N_OST + e]) * sm[N_OST + 64 + e] * gj + bj;
                sm[N_OH + e * 68 + j] = nv;
                if (n < Nn) x_out[(size_t)n * 64 + j] = nv;
            }
        }
        __syncthreads();
        {
#pragma unroll
            for (int ebk = 0; ebk < 4; ++ebk) {
                int e = (tid >> 4) + (ebk << 4);
                int n = t * 64 + e;
                if (n < Nn) {
                    float4 v = *(const float4*)(sm + N_OH + e * 68 + j4);
                    red_v4(g_gsum + (size_t)sbi[e] * 64 + j4, v);
                }
            }
        }
        __syncthreads();
    }
}

// ---------------- kernel 3: global MLP ----------------
#define G_OW1 0
#define G_OW2 8192
#define G_OB  12288
#define G_OX  12544
#define G_OH  16896
#define G_OST 21248
#define G_SMEM_BYTES (21376 * 4)

__global__ __launch_bounds__(256, 1) void glob_kernel(
    const float* __restrict__ u,
    const float* __restrict__ W1, const float* __restrict__ b1,
    const float* __restrict__ W2, const float* __restrict__ b2,
    const float* __restrict__ gm, const float* __restrict__ bt,
    float* __restrict__ u_out) {
    extern __shared__ float sm[];
    int tid = threadIdx.x;
    cp_smem<256>(sm + G_OW1, W1, 8192, tid);
    cp_smem<256>(sm + G_OW2, W2, 4096, tid);
    if (tid < 64) {
        sm[G_OB + tid] = b1[tid];       sm[G_OB + 64 + tid] = b2[tid];
        sm[G_OB + 128 + tid] = gm[tid]; sm[G_OB + 192 + tid] = bt[tid];
    }
    __syncthreads();
    const int i4 = (tid >> 4) << 2;
    const int j4 = (tid & 15) << 2;
    {
        int e = tid >> 2, q = tid & 3;
        float inv = 1.0f / fmaxf(g_gcnt[e], 1.0f);
#pragma unroll
        for (int tt = 0; tt < 8; ++tt) {
            int k0 = q * 32 + tt * 4;
            float4 v;
            if (k0 < 64) {
                v = ((const float4*)(u + (size_t)e * 64))[k0 >> 2];
            } else {
                v = ((const float4*)(g_gsum + (size_t)e * 64))[(k0 - 64) >> 2];
                v.x *= inv; v.y *= inv; v.z *= inv; v.w *= inv;
            }
            float* d = sm + G_OX + k0 * 68 + (e ^ SWZ(k0));
            d[0] = v.x; d[68] = v.y; d[136] = v.z; d[204] = v.w;
        }
    }
    __syncthreads();
    u64 acc[4][2];
    zero8(acc);
    gemmA2<128, 0>(sm + G_OX, sm + G_OW1, i4, j4, acc);
    storeH2(sm + G_OH, i4, j4, acc, sm + G_OB);
    __syncthreads();
    zero8(acc);
    gemmB2<64>(sm + G_OH, sm + G_OW2, i4, j4, acc);
    __syncthreads();
    storeH2(sm + G_OH, i4, j4, acc, sm + G_OB + 64);
    __syncthreads();
    ln_stats(sm + G_OH, sm + G_OST, tid);
    __syncthreads();
    {
        int j = tid & 63, g2 = tid >> 6;
        float gj = sm[G_OB + 128 + j], bj = sm[G_OB + 192 + j];
#pragma unroll
        for (int r = 0; r < 16; ++r) {
            int e = g2 * 16 + r;
            float v = sm[G_OH + e * 68 + j];
            float nv = (v - sm[G_OST + e]) * sm[G_OST + 64 + e] * gj + bj;
            u_out[(size_t)e * 64 + j] = nv;
        }
    }
}

// ---------------- launch ----------------
extern "C" void kernel_launch(void* const* d_in, const int* in_sizes, int n_in,
                              void* d_out, int out_size) {
    const float* x = (const float*)d_in[0];
    const int* ei = (const int*)d_in[1];
    const float* ea = (const float*)d_in[2];
    const float* u = (const float*)d_in[3];
    const int* batch = (const int*)d_in[4];

    const float* eW1 = (const float*)d_in[5];
    const float* eb1 = (const float*)d_in[6];
    const float* eW2 = (const float*)d_in[7];
    const float* eb2 = (const float*)d_in[8];
    const float* egm = (const float*)d_in[9];
    const float* ebt = (const float*)d_in[10];
    const float* n1W1 = (const float*)d_in[11];
    const float* n1b1 = (const float*)d_in[12];
    const float* n1W2 = (const float*)d_in[13];
    const float* n1b2 = (const float*)d_in[14];
    const float* n1g = (const float*)d_in[15];
    const float* n1bt = (const float*)d_in[16];
    const float* n2W1 = (const float*)d_in[17];
    const float* n2b1 = (const float*)d_in[18];
    const float* n2W2 = (const float*)d_in[19];
    const float* n2b2 = (const float*)d_in[20];
    const float* n2g = (const float*)d_in[21];
    const float* n2bt = (const float*)d_in[22];
    const float* gW1 = (const float*)d_in[23];
    const float* gb1 = (const float*)d_in[24];
    const float* gW2 = (const float*)d_in[25];
    const float* gb2 = (const float*)d_in[26];
    const float* gg = (const float*)d_in[27];
    const float* gbt = (const float*)d_in[28];

    float* out = (float*)d_out;
    float* x_out = out;                               // (N, 64)
    float* e_out = out + (size_t)Nn * 64;             // (E, 64)
    float* u_out = out + (size_t)(Nn + Ee) * 64;      // (G, 64)

    cudaFuncSetAttribute(node_pre_kernel, cudaFuncAttributeMaxDynamicSharedMemorySize, P_SMEM_BYTES);
    cudaFuncSetAttribute(edge_node1_kernel, cudaFuncAttributeMaxDynamicSharedMemorySize, E_SMEM_BYTES);
    cudaFuncSetAttribute(node2_kernel, cudaFuncAttributeMaxDynamicSharedMemorySize, N_SMEM_BYTES);
    cudaFuncSetAttribute(glob_kernel, cudaFuncAttributeMaxDynamicSharedMemorySize, G_SMEM_BYTES);

    zero_kernel<<<2048, 256>>>();
    pu_kernel<<<1, 256>>>(u, eW1, n2W1, n2b1);
    node_pre_kernel<<<(Nn + 63) / 64, 256, P_SMEM_BYTES>>>(x, batch, eW1, eb1, n1W1, n1b1);
    edge_node1_kernel<<<2368, 256, E_SMEM_BYTES>>>(
        ei, ea, eW1, eb2, eW2, egm, ebt,
        n1W1, n1W2, n1b2, n1g, n1bt,
        e_out);
    node2_kernel<<<1184, 256, N_SMEM_BYTES>>>(
        batch, n2W1, n2W2, n2b2, n2g, n2bt, x_out);
    glob_kernel<<<1, 256, G_SMEM_BYTES>>>(
        u, gW1, gb1, gW2, gb2, gg, gbt, u_out);
}

// round 15
// speedup vs baseline: 1.0773x; 1.0773x over previous
#include <cuda_runtime.h>

#define Hdim 64
#define Nn   100000
#define Ee   1000000
#define Gg   64

typedef unsigned long long u64;

// ---------------- scratch ----------------
__device__ float g_aggsum[Nn * Hdim];
__device__ float g_aggcnt[Nn];
__device__ float g_gsum[Gg * Hdim];
__device__ float g_gcnt[Gg];
__device__ float g_PUe[Gg * Hdim];     // u @ eW1d
__device__ float g_PUn2[Gg * Hdim];    // u @ n2W1b + n2b1
__device__ float g_P1p[Nn * Hdim];     // x @ eW1a + PUe[batch] + eb1
__device__ float g_P2Q[Nn * 2 * Hdim]; // [x @ eW1b | x @ n1W1a + n1b1]
__device__ float g_LN1g[64];           // egm @ n1W1b
__device__ float g_LN1c[64];           // ebt @ n1W1b

// ---------------- packed f32x2 helpers ----------------
__device__ __forceinline__ u64 bcast2(float x) {
    u64 r; unsigned xi = __float_as_uint(x);
    asm("mov.b64 %0, {%1, %2};" : "=l"(r) : "r"(xi), "r"(xi));
    return r;
}
__device__ __forceinline__ void ffma2(u64& d, u64 a, u64 b) {
    asm("fma.rn.f32x2 %0, %1, %2, %0;" : "+l"(d) : "l"(a), "l"(b));
}
__device__ __forceinline__ float2 unpack2(u64 v) {
    unsigned lo, hi;
    asm("mov.b64 {%0, %1}, %2;" : "=r"(lo), "=r"(hi) : "l"(v));
    return make_float2(__uint_as_float(lo), __uint_as_float(hi));
}
__device__ __forceinline__ float fsel(float4 v, int i) {
    return i == 0 ? v.x : (i == 1 ? v.y : (i == 2 ? v.z : v.w));
}
__device__ __forceinline__ float gelu_f(float v) {
    return 0.5f * v * (1.0f + erff(v * 0.7071067811865476f));
}
__device__ __forceinline__ void zero8(u64 (&a)[4][2]) {
#pragma unroll
    for (int i = 0; i < 4; ++i) { a[i][0] = 0ULL; a[i][1] = 0ULL; }
}
template <int NT>
__device__ __forceinline__ void cp_smem(float* dst, const float* src, int nfloats, int tid) {
    const float4* s4 = (const float4*)src; float4* d4 = (float4*)dst;
    for (int i = tid; i < (nfloats >> 2); i += NT) d4[i] = s4[i];
}

// row-major GEMM (4i x 4j packed): X row-major stride LD, float4 loads along k
template <int K, int LD>
__device__ __forceinline__ void gemmB2(const float* __restrict__ Hs, const float* __restrict__ Ws,
                                       int i4, int j4, u64 (&a)[4][2]) {
#pragma unroll 2
    for (int k0 = 0; k0 < K; k0 += 4) {
        float4 h0 = *(const float4*)(Hs + (i4 + 0) * LD + k0);
        float4 h1 = *(const float4*)(Hs + (i4 + 1) * LD + k0);
        float4 h2 = *(const float4*)(Hs + (i4 + 2) * LD + k0);
        float4 h3 = *(const float4*)(Hs + (i4 + 3) * LD + k0);
#pragma unroll
        for (int dk = 0; dk < 4; ++dk) {
            ulonglong2 wv = *(const ulonglong2*)(Ws + (k0 + dk) * 64 + j4);
            u64 x0 = bcast2(fsel(h0, dk)), x1 = bcast2(fsel(h1, dk));
            u64 x2 = bcast2(fsel(h2, dk)), x3 = bcast2(fsel(h3, dk));
            ffma2(a[0][0], x0, wv.x); ffma2(a[0][1], x0, wv.y);
            ffma2(a[1][0], x1, wv.x); ffma2(a[1][1], x1, wv.y);
            ffma2(a[2][0], x2, wv.x); ffma2(a[2][1], x2, wv.y);
            ffma2(a[3][0], x3, wv.x); ffma2(a[3][1], x3, wv.y);
        }
    }
}

__device__ __forceinline__ void storeH2(float* __restrict__ Hs, int i4, int j4,
                                        u64 (&a)[4][2], const float* __restrict__ bias) {
    float4 b = *(const float4*)(bias + j4);
#pragma unroll
    for (int r = 0; r < 4; ++r) {
        float2 p0 = unpack2(a[r][0]); float2 p1 = unpack2(a[r][1]);
        float* row = Hs + (i4 + r) * 68 + j4;
        row[0] = gelu_f(p0.x + b.x); row[1] = gelu_f(p0.y + b.y);
        row[2] = gelu_f(p1.x + b.z); row[3] = gelu_f(p1.y + b.w);
    }
}
__device__ __forceinline__ void storeH2off(float* __restrict__ Hs, int i4, int j4,
                                           u64 (&a)[4][2], const float4* __restrict__ off) {
#pragma unroll
    for (int r = 0; r < 4; ++r) {
        float2 p0 = unpack2(a[r][0]); float2 p1 = unpack2(a[r][1]);
        float* row = Hs + (i4 + r) * 68 + j4;
        row[0] = gelu_f(p0.x + off[r].x); row[1] = gelu_f(p0.y + off[r].y);
        row[2] = gelu_f(p1.x + off[r].z); row[3] = gelu_f(p1.y + off[r].w);
    }
}
__device__ __forceinline__ void ln_stats(const float* __restrict__ Hs, float* __restrict__ st, int tid) {
    if (tid < 64) {
        float s = 0.0f, s2 = 0.0f;
#pragma unroll
        for (int c = 0; c < 16; ++c) {
            float4 v = *(const float4*)(Hs + tid * 68 + 4 * c);
            s += v.x + v.y + v.z + v.w;
            s2 += v.x * v.x + v.y * v.y + v.z * v.z + v.w * v.w;
        }
        float m = s * (1.0f / 64.0f);
        float var = s2 * (1.0f / 64.0f) - m * m;
        st[tid] = m;
        st[64 + tid] = rsqrtf(fmaxf(var, 0.0f) + 1e-5f);
    }
}
__device__ __forceinline__ void red_v4(float* p, float4 v) {
    asm volatile("red.global.add.v4.f32 [%0], {%1,%2,%3,%4};"
                 :: "l"(p), "f"(v.x), "f"(v.y), "f"(v.z), "f"(v.w) : "memory");
}

// ---------------- zero scratch ----------------
__global__ void zero_kernel() {
    int total = Nn * Hdim + Nn + Gg * Hdim + Gg;
    for (int i = blockIdx.x * blockDim.x + threadIdx.x; i < total; i += gridDim.x * blockDim.x) {
        if (i < Nn * Hdim) g_aggsum[i] = 0.0f;
        else if (i < Nn * Hdim + Nn) g_aggcnt[i - Nn * Hdim] = 0.0f;
        else if (i < Nn * Hdim + Nn + Gg * Hdim) g_gsum[i - Nn * Hdim - Nn] = 0.0f;
        else g_gcnt[i - Nn * Hdim - Nn - Gg * Hdim] = 0.0f;
    }
}

// ---------------- P0: per-graph precompute + LN-fold vectors ----------------
__global__ __launch_bounds__(256, 1) void pu_kernel(
    const float* __restrict__ u, const float* __restrict__ eW1,
    const float* __restrict__ n2W1, const float* __restrict__ n2b1,
    const float* __restrict__ n1W1, const float* __restrict__ egm,
    const float* __restrict__ ebt) {
    __shared__ float su[4096], sw1[4096], sw2[4096];
    int tid = threadIdx.x;
    cp_smem<256>(su, u, 4096, tid);
    cp_smem<256>(sw1, eW1 + 192 * 64, 4096, tid);   // eW1d
    cp_smem<256>(sw2, n2W1 + 64 * 64, 4096, tid);   // n2W1b
    __syncthreads();
    int g = tid >> 2, q = tid & 3;
#pragma unroll 4
    for (int jj = 0; jj < 16; ++jj) {
        int j = q * 16 + jj;
        float s1 = 0.0f, s2 = 0.0f;
#pragma unroll 4
        for (int k = 0; k < 64; ++k) {
            float uv = su[g * 64 + k];
            s1 += uv * sw1[k * 64 + j];
            s2 += uv * sw2[k * 64 + j];
        }
        g_PUe[g * 64 + j] = s1;
        g_PUn2[g * 64 + j] = s2 + n2b1[j];
    }
    // LN-fold vectors: gv = egm @ n1W1b, cv = ebt @ n1W1b
    if (tid < 64) {
        float s1 = 0.0f, s2 = 0.0f;
        for (int k = 0; k < 64; ++k) {
            float w = n1W1[(64 + k) * 64 + tid];
            s1 += egm[k] * w;
            s2 += ebt[k] * w;
        }
        g_LN1g[tid] = s1;
        g_LN1c[tid] = s2;
    }
}

// ---------------- P1: per-node precompute ----------------
#define P_OWA 0
#define P_OWB 4096
#define P_OWQ 8192
#define P_OBp 12288
#define P_OX  12416
#define P_SBT 16768
#define P_SMEM_BYTES (16832 * 4)

__global__ __launch_bounds__(256, 2) void node_pre_kernel(
    const float* __restrict__ x, const int* __restrict__ batch,
    const float* __restrict__ eW1, const float* __restrict__ eb1,
    const float* __restrict__ nW1, const float* __restrict__ nb1) {
    extern __shared__ float sm[];
    int tid = threadIdx.x;
    cp_smem<256>(sm + P_OWA, eW1, 4096, tid);
    cp_smem<256>(sm + P_OWB, eW1 + 4096, 4096, tid);
    cp_smem<256>(sm + P_OWQ, nW1, 4096, tid);
    if (tid < 64) { sm[P_OBp + tid] = eb1[tid]; sm[P_OBp + 64 + tid] = nb1[tid]; }
    __syncthreads();
    const int i4 = (tid >> 4) << 2, j4 = (tid & 15) << 2;
    int* sbt = (int*)(sm + P_SBT);
    int t = blockIdx.x;
    {
        int e = tid >> 2, q = tid & 3;
        int n = t * 64 + e;
        bool valid = n < Nn;
        if (q == 0) sbt[e] = valid ? batch[n] : 0;
        float4* d = (float4*)(sm + P_OX + e * 68 + q * 16);
        const float4* s4 = (const float4*)(x + (size_t)n * 64 + q * 16);
#pragma unroll
        for (int i = 0; i < 4; ++i)
            d[i] = valid ? s4[i] : make_float4(0.f, 0.f, 0.f, 0.f);
    }
    __syncthreads();
    u64 acc[4][2];
    zero8(acc);
    gemmB2<64, 68>(sm + P_OX, sm + P_OWA, i4, j4, acc);
#pragma unroll
    for (int r = 0; r < 4; ++r) {
        int n2 = t * 64 + i4 + r;
        if (n2 < Nn) {
            int b = sbt[i4 + r];
            float4 pu = *(const float4*)(g_PUe + b * 64 + j4);
            float4 b1 = *(const float4*)(sm + P_OBp + j4);
            float2 p0 = unpack2(acc[r][0]); float2 p1 = unpack2(acc[r][1]);
            *(float4*)(g_P1p + (size_t)n2 * 64 + j4) =
                make_float4(p0.x + pu.x + b1.x, p0.y + pu.y + b1.y, p1.x + pu.z + b1.z, p1.y + pu.w + b1.w);
        }
    }
    zero8(acc);
    gemmB2<64, 68>(sm + P_OX, sm + P_OWB, i4, j4, acc);
#pragma unroll
    for (int r = 0; r < 4; ++r) {
        int n2 = t * 64 + i4 + r;
        if (n2 < Nn) {
            float2 p0 = unpack2(acc[r][0]); float2 p1 = unpack2(acc[r][1]);
            *(float4*)(g_P2Q + (size_t)n2 * 128 + j4) = make_float4(p0.x, p0.y, p1.x, p1.y);
        }
    }
    zero8(acc);
    gemmB2<64, 68>(sm + P_OX, sm + P_OWQ, i4, j4, acc);
#pragma unroll
    for (int r = 0; r < 4; ++r) {
        int n2 = t * 64 + i4 + r;
        if (n2 < Nn) {
            float4 b1 = *(const float4*)(sm + P_OBp + 64 + j4);
            float2 p0 = unpack2(acc[r][0]); float2 p1 = unpack2(acc[r][1]);
            *(float4*)(g_P2Q + (size_t)n2 * 128 + 64 + j4) =
                make_float4(p0.x + b1.x, p0.y + b1.y, p1.x + b1.z, p1.y + b1.w);
        }
    }
}

// ---------------- kernel 1: fused edge+message (row-major, LN-folded) ----------------
#define E_WE1 0
#define E_WE2 4096
#define E_WN1 8192
#define E_WN2 12288
#define E_BS  16384
#define E_B0  16896
#define E_B1  21248
#define E_ST  25600
#define E_IDX 25728
#define E_SMEM_BYTES (25856 * 4)

__global__ __launch_bounds__(256, 2) void edge_node1_kernel(
    const int* __restrict__ ei, const float* __restrict__ ea,
    const float* __restrict__ eW1, const float* __restrict__ eW2,
    const float* __restrict__ n1W1, const float* __restrict__ n1W2,
    const float* __restrict__ eb2v, const float* __restrict__ egm,
    const float* __restrict__ ebt, const float* __restrict__ nb2v,
    const float* __restrict__ ngm, const float* __restrict__ nbt,
    float* __restrict__ edge_out) {
    extern __shared__ float sm[];
    int tid = threadIdx.x;
    cp_smem<256>(sm + E_WE1, eW1 + 8192, 4096, tid);   // eW1c
    cp_smem<256>(sm + E_WE2, eW2, 4096, tid);
    // WN1 = diag(egm) * n1W1b  (scaled at load)
    for (int i = tid; i < 4096; i += 256)
        sm[E_WN1 + i] = n1W1[4096 + i] * egm[i >> 6];
    cp_smem<256>(sm + E_WN2, n1W2, 4096, tid);
    if (tid < 64) {
        sm[E_BS + tid] = eb2v[tid];        sm[E_BS + 64 + tid] = egm[tid];
        sm[E_BS + 128 + tid] = ebt[tid];   sm[E_BS + 192 + tid] = nb2v[tid];
        sm[E_BS + 256 + tid] = ngm[tid];   sm[E_BS + 320 + tid] = nbt[tid];
        sm[E_BS + 384 + tid] = g_LN1g[tid]; sm[E_BS + 448 + tid] = g_LN1c[tid];
    }
    __syncthreads();

    const int i4 = (tid >> 4) << 2;
    const int j4 = (tid & 15) << 2;
    int* sidx = (int*)(sm + E_IDX);
    float* ST = sm + E_ST;

    for (int t = blockIdx.x; t < Ee / 64; t += gridDim.x) {
        // a) indices + contiguous ea gather (row-major, stride 68)
        if (tid < 64) {
            int eg = t * 64 + tid;
            int r = ei[eg], c = ei[Ee + eg];
            sidx[tid] = r; sidx[64 + tid] = c;
            atomicAdd(&g_aggcnt[r], 1.0f);
        }
        {
            int e = tid >> 2, q = tid & 3;
            const float4* s4 = (const float4*)(ea + (size_t)(t * 64 + e) * 64 + q * 16);
            float4* d = (float4*)(sm + E_B0 + e * 68 + q * 16);
            d[0] = s4[0]; d[1] = s4[1]; d[2] = s4[2]; d[3] = s4[3];
        }
        __syncthreads(); // S1

        // offset prefetch (regs) + edge layer 1
        float4 off1[4], off2[4];
#pragma unroll
        for (int r = 0; r < 4; ++r) {
            int row = sidx[i4 + r], col = sidx[64 + i4 + r];
            float4 a1 = *(const float4*)(g_P1p + (size_t)row * 64 + j4);
            float4 a2 = *(const float4*)(g_P2Q + (size_t)col * 128 + j4);
            off1[r] = make_float4(a1.x + a2.x, a1.y + a2.y, a1.z + a2.z, a1.w + a2.w);
            off2[r] = *(const float4*)(g_P2Q + (size_t)col * 128 + 64 + j4);
        }
        u64 acc[4][2];
        zero8(acc);
        gemmB2<64, 68>(sm + E_B0, sm + E_WE1, i4, j4, acc);
        __syncthreads(); // S2 (all B0 reads done)
        storeH2off(sm + E_B0, i4, j4, acc, off1);  // B0 := h1
        __syncthreads(); // S3
        // edge layer 2 -> B1
        zero8(acc);
        gemmB2<64, 68>(sm + E_B0, sm + E_WE2, i4, j4, acc);
        storeH2(sm + E_B1, i4, j4, acc, sm + E_BS + 0);  // B1 := h2
        __syncthreads(); // S4
        ln_stats(sm + E_B1, ST, tid);
        __syncthreads(); // S5
        // edge_out write + msg layer 1 (LN folded): all reads from B1, write B0
        {
            int j = tid & 63, g2 = tid >> 6;
            float gj = sm[E_BS + 64 + j], bj = sm[E_BS + 128 + j];
            float* eb = edge_out + (size_t)t * 4096;
#pragma unroll
            for (int r = 0; r < 16; ++r) {
                int e = g2 * 16 + r;
                float v = sm[E_B1 + e * 68 + j];
                eb[(size_t)e * 64 + j] = (v - ST[e]) * ST[64 + e] * gj + bj;
            }
        }
        zero8(acc);
        gemmB2<64, 68>(sm + E_B1, sm + E_WN1, i4, j4, acc);  // h2 @ (diag(egm) nW1b)
        {
            float4 gv4 = *(const float4*)(sm + E_BS + 384 + j4);
            float4 cv4 = *(const float4*)(sm + E_BS + 448 + j4);
#pragma unroll
            for (int r = 0; r < 4; ++r) {
                float m = ST[i4 + r], rs = ST[64 + i4 + r];
                float rm = rs * m;
                float2 p0 = unpack2(acc[r][0]); float2 p1 = unpack2(acc[r][1]);
                float* row = sm + E_B0 + (i4 + r) * 68 + j4;
                row[0] = gelu_f(rs * p0.x - rm * gv4.x + cv4.x + off2[r].x);
                row[1] = gelu_f(rs * p0.y - rm * gv4.y + cv4.y + off2[r].y);
                row[2] = gelu_f(rs * p1.x - rm * gv4.z + cv4.z + off2[r].z);
                row[3] = gelu_f(rs * p1.y - rm * gv4.w + cv4.w + off2[r].w);
            }
        }
        __syncthreads(); // S6
        // msg layer 2 -> B1
        zero8(acc);
        gemmB2<64, 68>(sm + E_B0, sm + E_WN2, i4, j4, acc);
        storeH2(sm + E_B1, i4, j4, acc, sm + E_BS + 192);
        __syncthreads(); // S7
        ln_stats(sm + E_B1, ST, tid);
        __syncthreads(); // S8
        // scatter
        {
            float4 g4 = *(const float4*)(sm + E_BS + 256 + j4);
            float4 b4 = *(const float4*)(sm + E_BS + 320 + j4);
#pragma unroll
            for (int ebk = 0; ebk < 4; ++ebk) {
                int e = (tid >> 4) + (ebk << 4);
                float mn = ST[e], rs = ST[64 + e];
                float4 v = *(const float4*)(sm + E_B1 + e * 68 + j4);
                v.x = (v.x - mn) * rs * g4.x + b4.x;
                v.y = (v.y - mn) * rs * g4.y + b4.y;
                v.z = (v.z - mn) * rs * g4.z + b4.z;
                v.w = (v.w - mn) * rs * g4.w + b4.w;
                red_v4(g_aggsum + (size_t)sidx[e] * 64 + j4, v);
            }
        }
        __syncthreads(); // S9
    }
}

// ---------------- kernel 2: node update ----------------
#define N_OW1 0
#define N_OW2 4096
#define N_OB  8192
#define N_OX  8384
#define N_OH  12736
#define N_OST 17088
#define N_OBI 17216
#define N_SMEM_BYTES (17280 * 4)

__global__ __launch_bounds__(256, 2) void node2_kernel(
    const int* __restrict__ batch,
    const float* __restrict__ W1, const float* __restrict__ W2,
    const float* __restrict__ b2, const float* __restrict__ gm, const float* __restrict__ bt,
    float* __restrict__ x_out) {
    extern __shared__ float sm[];
    int tid = threadIdx.x;
    cp_smem<256>(sm + N_OW1, W1, 4096, tid);
    cp_smem<256>(sm + N_OW2, W2, 4096, tid);
    if (tid < 64) {
        sm[N_OB + tid] = b2[tid]; sm[N_OB + 64 + tid] = gm[tid]; sm[N_OB + 128 + tid] = bt[tid];
    }
    __syncthreads();
    const int i4 = (tid >> 4) << 2, j4 = (tid & 15) << 2;
    int* sbi = (int*)(sm + N_OBI);
    const int nTiles = (Nn + 63) / 64;
    for (int t = blockIdx.x; t < nTiles; t += gridDim.x) {
        {
            int e = tid >> 2, q = tid & 3;
            int n = t * 64 + e;
            bool valid = n < Nn;
            if (q == 0) {
                int b = valid ? batch[n] : 0;
                sbi[e] = b;
                if (valid) atomicAdd(&g_gcnt[b], 1.0f);
            }
            float inv = valid ? 1.0f / fmaxf(g_aggcnt[n], 1.0f) : 1.0f;
            float4* d = (float4*)(sm + N_OX + e * 68 + q * 16);
            const float4* s4 = (const float4*)(g_aggsum + (size_t)n * 64 + q * 16);
#pragma unroll
            for (int i = 0; i < 4; ++i) {
                float4 v = valid ? s4[i] : make_float4(0.f, 0.f, 0.f, 0.f);
                v.x *= inv; v.y *= inv; v.z *= inv; v.w *= inv;
                d[i] = v;
            }
        }
        __syncthreads();
        float4 off[4];
#pragma unroll
        for (int r = 0; r < 4; ++r) {
            int n2 = t * 64 + i4 + r;
            off[r] = make_float4(0.f, 0.f, 0.f, 0.f);
            if (n2 < Nn) off[r] = *(const float4*)(g_PUn2 + sbi[i4 + r] * 64 + j4);
        }
        u64 acc[4][2];
        zero8(acc);
        gemmB2<64, 68>(sm + N_OX, sm + N_OW1, i4, j4, acc);
        storeH2off(sm + N_OH, i4, j4, acc, off);
        __syncthreads();
        zero8(acc);
        gemmB2<64, 68>(sm + N_OH, sm + N_OW2, i4, j4, acc);
        __syncthreads();
        storeH2(sm + N_OH, i4, j4, acc, sm + N_OB);
        __syncthreads();
        ln_stats(sm + N_OH, sm + N_OST, tid);
        __syncthreads();
        {
            int j = tid & 63, g2 = tid >> 6;
            float gj = sm[N_OB + 64 + j], bj = sm[N_OB + 128 + j];
#pragma unroll
            for (int r = 0; r < 16; ++r) {
                int e = g2 * 16 + r;
                int n = t * 64 + e;
                float v = sm[N_OH + e * 68 + j];
                float nv = (v - sm[N_OST + e]) * sm[N_OST + 64 + e] * gj + bj;
                sm[N_OH + e * 68 + j] = nv;
                if (n < Nn) x_out[(size_t)n * 64 + j] = nv;
            }
        }
        __syncthreads();
        {
#pragma unroll
            for (int ebk = 0; ebk < 4; ++ebk) {
                int e = (tid >> 4) + (ebk << 4);
                int n = t * 64 + e;
                if (n < Nn) {
                    float4 v = *(const float4*)(sm + N_OH + e * 68 + j4);
                    red_v4(g_gsum + (size_t)sbi[e] * 64 + j4, v);
                }
            }
        }
        __syncthreads();
    }
}

// ---------------- kernel 3: global MLP ----------------
#define G_OW1 0
#define G_OW2 8192
#define G_OB  12288
#define G_OX  12544
#define G_OH  21056
#define G_OST 25408
#define G_SMEM_BYTES (25536 * 4)

__global__ __launch_bounds__(256, 1) void glob_kernel(
    const float* __restrict__ u,
    const float* __restrict__ W1, const float* __restrict__ b1,
    const float* __restrict__ W2, const float* __restrict__ b2,
    const float* __restrict__ gm, const float* __restrict__ bt,
    float* __restrict__ u_out) {
    extern __shared__ float sm[];
    int tid = threadIdx.x;
    cp_smem<256>(sm + G_OW1, W1, 8192, tid);
    cp_smem<256>(sm + G_OW2, W2, 4096, tid);
    if (tid < 64) {
        sm[G_OB + tid] = b1[tid];       sm[G_OB + 64 + tid] = b2[tid];
        sm[G_OB + 128 + tid] = gm[tid]; sm[G_OB + 192 + tid] = bt[tid];
    }
    __syncthreads();
    const int i4 = (tid >> 4) << 2, j4 = (tid & 15) << 2;
    {
        // row layout (stride 132): cols [0,64) = u, cols [64,128) = agg/cnt
        int e = tid >> 2, q = tid & 3;
        float inv = 1.0f / fmaxf(g_gcnt[e], 1.0f);
        const float4* su = (const float4*)(u + (size_t)e * 64 + q * 16);
        const float4* sg = (const float4*)(g_gsum + (size_t)e * 64 + q * 16);
        float4* du = (float4*)(sm + G_OX + e * 132 + q * 16);
        float4* dg = (float4*)(sm + G_OX + e * 132 + 64 + q * 16);
#pragma unroll
        for (int i = 0; i < 4; ++i) du[i] = su[i];
#pragma unroll
        for (int i = 0; i < 4; ++i) {
            float4 v = sg[i];
            v.x *= inv; v.y *= inv; v.z *= inv; v.w *= inv;
            dg[i] = v;
        }
    }
    __syncthreads();
    u64 acc[4][2];
    zero8(acc);
    gemmB2<128, 132>(sm + G_OX, sm + G_OW1, i4, j4, acc);
    storeH2(sm + G_OH, i4, j4, acc, sm + G_OB);
    __syncthreads();
    zero8(acc);
    gemmB2<64, 68>(sm + G_OH, sm + G_OW2, i4, j4, acc);
    __syncthreads();
    storeH2(sm + G_OH, i4, j4, acc, sm + G_OB + 64);
    __syncthreads();
    ln_stats(sm + G_OH, sm + G_OST, tid);
    __syncthreads();
    {
        int j = tid & 63, g2 = tid >> 6;
        float gj = sm[G_OB + 128 + j], bj = sm[G_OB + 192 + j];
#pragma unroll
        for (int r = 0; r < 16; ++r) {
            int e = g2 * 16 + r;
            float v = sm[G_OH + e * 68 + j];
            float nv = (v - sm[G_OST + e]) * sm[G_OST + 64 + e] * gj + bj;
            u_out[(size_t)e * 64 + j] = nv;
        }
    }
}

// ---------------- launch ----------------
extern "C" void kernel_launch(void* const* d_in, const int* in_sizes, int n_in,
                              void* d_out, int out_size) {
    const float* x = (const float*)d_in[0];
    const int* ei = (const int*)d_in[1];
    const float* ea = (const float*)d_in[2];
    const float* u = (const float*)d_in[3];
    const int* batch = (const int*)d_in[4];
    const float* eW1 = (const float*)d_in[5];
    const float* eb1 = (const float*)d_in[6];
    const float* eW2 = (const float*)d_in[7];
    const float* eb2 = (const float*)d_in[8];
    const float* egm = (const float*)d_in[9];
    const float* ebt = (const float*)d_in[10];
    const float* n1W1 = (const float*)d_in[11];
    const float* n1b1 = (const float*)d_in[12];
    const float* n1W2 = (const float*)d_in[13];
    const float* n1b2 = (const float*)d_in[14];
    const float* n1g = (const float*)d_in[15];
    const float* n1bt = (const float*)d_in[16];
    const float* n2W1 = (const float*)d_in[17];
    const float* n2b1 = (const float*)d_in[18];
    const float* n2W2 = (const float*)d_in[19];
    const float* n2b2 = (const float*)d_in[20];
    const float* n2g = (const float*)d_in[21];
    const float* n2bt = (const float*)d_in[22];
    const float* gW1 = (const float*)d_in[23];
    const float* gb1 = (const float*)d_in[24];
    const float* gW2 = (const float*)d_in[25];
    const float* gb2 = (const float*)d_in[26];
    const float* gg = (const float*)d_in[27];
    const float* gbt = (const float*)d_in[28];

    float* out = (float*)d_out;
    float* x_out = out;
    float* e_out = out + (size_t)Nn * 64;
    float* u_out = out + (size_t)(Nn + Ee) * 64;

    cudaFuncSetAttribute(node_pre_kernel, cudaFuncAttributeMaxDynamicSharedMemorySize, P_SMEM_BYTES);
    cudaFuncSetAttribute(edge_node1_kernel, cudaFuncAttributeMaxDynamicSharedMemorySize, E_SMEM_BYTES);
    cudaFuncSetAttribute(node2_kernel, cudaFuncAttributeMaxDynamicSharedMemorySize, N_SMEM_BYTES);
    cudaFuncSetAttribute(glob_kernel, cudaFuncAttributeMaxDynamicSharedMemorySize, G_SMEM_BYTES);

    zero_kernel<<<2048, 256>>>();
    pu_kernel<<<1, 256>>>(u, eW1, n2W1, n2b1, n1W1, egm, ebt);
    node_pre_kernel<<<(Nn + 63) / 64, 256, P_SMEM_BYTES>>>(x, batch, eW1, eb1, n1W1, n1b1);
    edge_node1_kernel<<<592, 256, E_SMEM_BYTES>>>(
        ei, ea, eW1, eW2, n1W1, n1W2,
        eb2, egm, ebt, n1b2, n1g, n1bt, e_out);
    node2_kernel<<<1184, 256, N_SMEM_BYTES>>>(
        batch, n2W1, n2W2, n2b2, n2g, n2bt, x_out);
    glob_kernel<<<1, 256, G_SMEM_BYTES>>>(
        u, gW1, gb1, gW2, gb2, gg, gbt, u_out);
}

// round 17
// speedup vs baseline: 1.1453x; 1.0631x over previous
#include <cuda_runtime.h>

#define Hdim 64
#define Nn   100000
#define Ee   1000000
#define Gg   64

typedef unsigned long long u64;

// ---------------- scratch ----------------
__device__ float g_aggsum[Nn * Hdim];
__device__ float g_aggcnt[Nn];
__device__ float g_gsum[Gg * Hdim];
__device__ float g_gcnt[Gg];
__device__ float g_PUe[Gg * Hdim];     // u @ eW1d
__device__ float g_PUn2[Gg * Hdim];    // u @ n2W1b + n2b1
__device__ float g_P1p[Nn * Hdim];     // x @ eW1a + PUe[batch] + eb1
__device__ float g_P2Q[Nn * 2 * Hdim]; // [x @ eW1b | x @ n1W1a + n1b1]
__device__ float g_LN1g[64];           // egm @ n1W1b
__device__ float g_LN1c[64];           // ebt @ n1W1b

// ---------------- packed f32x2 helpers ----------------
__device__ __forceinline__ u64 bcast2(float x) {
    u64 r; unsigned xi = __float_as_uint(x);
    asm("mov.b64 %0, {%1, %2};" : "=l"(r) : "r"(xi), "r"(xi));
    return r;
}
__device__ __forceinline__ void ffma2(u64& d, u64 a, u64 b) {
    asm("fma.rn.f32x2 %0, %1, %2, %0;" : "+l"(d) : "l"(a), "l"(b));
}
__device__ __forceinline__ float2 unpack2(u64 v) {
    unsigned lo, hi;
    asm("mov.b64 {%0, %1}, %2;" : "=r"(lo), "=r"(hi) : "l"(v));
    return make_float2(__uint_as_float(lo), __uint_as_float(hi));
}
__device__ __forceinline__ float fsel(float4 v, int i) {
    return i == 0 ? v.x : (i == 1 ? v.y : (i == 2 ? v.z : v.w));
}
__device__ __forceinline__ float gelu_f(float v) {
    return 0.5f * v * (1.0f + erff(v * 0.7071067811865476f));
}
__device__ __forceinline__ void zero8(u64 (&a)[4][2]) {
#pragma unroll
    for (int i = 0; i < 4; ++i) { a[i][0] = 0ULL; a[i][1] = 0ULL; }
}
template <int NT>
__device__ __forceinline__ void cp_smem(float* dst, const float* src, int nfloats, int tid) {
    const float4* s4 = (const float4*)src; float4* d4 = (float4*)dst;
    for (int i = tid; i < (nfloats >> 2); i += NT) d4[i] = s4[i];
}
#define HBAR(id) asm volatile("bar.sync %0, %1;" :: "r"(id), "r"(128) : "memory")

// row-major GEMM (4i x 4j packed): X row-major stride LD, float4 loads along k
template <int K, int LD>
__device__ __forceinline__ void gemmB2(const float* __restrict__ Hs, const float* __restrict__ Ws,
                                       int i4, int j4, u64 (&a)[4][2]) {
#pragma unroll 2
    for (int k0 = 0; k0 < K; k0 += 4) {
        float4 h0 = *(const float4*)(Hs + (i4 + 0) * LD + k0);
        float4 h1 = *(const float4*)(Hs + (i4 + 1) * LD + k0);
        float4 h2 = *(const float4*)(Hs + (i4 + 2) * LD + k0);
        float4 h3 = *(const float4*)(Hs + (i4 + 3) * LD + k0);
#pragma unroll
        for (int dk = 0; dk < 4; ++dk) {
            ulonglong2 wv = *(const ulonglong2*)(Ws + (k0 + dk) * 64 + j4);
            u64 x0 = bcast2(fsel(h0, dk)), x1 = bcast2(fsel(h1, dk));
            u64 x2 = bcast2(fsel(h2, dk)), x3 = bcast2(fsel(h3, dk));
            ffma2(a[0][0], x0, wv.x); ffma2(a[0][1], x0, wv.y);
            ffma2(a[1][0], x1, wv.x); ffma2(a[1][1], x1, wv.y);
            ffma2(a[2][0], x2, wv.x); ffma2(a[2][1], x2, wv.y);
            ffma2(a[3][0], x3, wv.x); ffma2(a[3][1], x3, wv.y);
        }
    }
}

__device__ __forceinline__ void storeH2(float* __restrict__ Hs, int i4, int j4,
                                        u64 (&a)[4][2], const float* __restrict__ bias) {
    float4 b = *(const float4*)(bias + j4);
#pragma unroll
    for (int r = 0; r < 4; ++r) {
        float2 p0 = unpack2(a[r][0]); float2 p1 = unpack2(a[r][1]);
        float* row = Hs + (i4 + r) * 68 + j4;
        row[0] = gelu_f(p0.x + b.x); row[1] = gelu_f(p0.y + b.y);
        row[2] = gelu_f(p1.x + b.z); row[3] = gelu_f(p1.y + b.w);
    }
}
__device__ __forceinline__ void storeH2off(float* __restrict__ Hs, int i4, int j4,
                                           u64 (&a)[4][2], const float4* __restrict__ off) {
#pragma unroll
    for (int r = 0; r < 4; ++r) {
        float2 p0 = unpack2(a[r][0]); float2 p1 = unpack2(a[r][1]);
        float* row = Hs + (i4 + r) * 68 + j4;
        row[0] = gelu_f(p0.x + off[r].x); row[1] = gelu_f(p0.y + off[r].y);
        row[2] = gelu_f(p1.x + off[r].z); row[3] = gelu_f(p1.y + off[r].w);
    }
}
// LN stats over 64 cols, 64 rows (full-CTA kernels)
__device__ __forceinline__ void ln_stats(const float* __restrict__ Hs, float* __restrict__ st, int tid) {
    if (tid < 64) {
        float s = 0.0f, s2 = 0.0f;
#pragma unroll
        for (int c = 0; c < 16; ++c) {
            float4 v = *(const float4*)(Hs + tid * 68 + 4 * c);
            s += v.x + v.y + v.z + v.w;
            s2 += v.x * v.x + v.y * v.y + v.z * v.z + v.w * v.w;
        }
        float m = s * (1.0f / 64.0f);
        float var = s2 * (1.0f / 64.0f) - m * m;
        st[tid] = m;
        st[64 + tid] = rsqrtf(fmaxf(var, 0.0f) + 1e-5f);
    }
}
// LN stats over 64 cols, 32 rows (half-tile): st[0..31]=mean, st[32..63]=rsig
__device__ __forceinline__ void ln_stats32(const float* __restrict__ Hs, float* __restrict__ st, int h) {
    if (h < 32) {
        float s = 0.0f, s2 = 0.0f;
#pragma unroll
        for (int c = 0; c < 16; ++c) {
            float4 v = *(const float4*)(Hs + h * 68 + 4 * c);
            s += v.x + v.y + v.z + v.w;
            s2 += v.x * v.x + v.y * v.y + v.z * v.z + v.w * v.w;
        }
        float m = s * (1.0f / 64.0f);
        float var = s2 * (1.0f / 64.0f) - m * m;
        st[h] = m;
        st[32 + h] = rsqrtf(fmaxf(var, 0.0f) + 1e-5f);
    }
}
__device__ __forceinline__ void red_v4(float* p, float4 v) {
    asm volatile("red.global.add.v4.f32 [%0], {%1,%2,%3,%4};"
                 :: "l"(p), "f"(v.x), "f"(v.y), "f"(v.z), "f"(v.w) : "memory");
}

// ---------------- zero scratch ----------------
__global__ void zero_kernel() {
    int total = Nn * Hdim + Nn + Gg * Hdim + Gg;
    for (int i = blockIdx.x * blockDim.x + threadIdx.x; i < total; i += gridDim.x * blockDim.x) {
        if (i < Nn * Hdim) g_aggsum[i] = 0.0f;
        else if (i < Nn * Hdim + Nn) g_aggcnt[i - Nn * Hdim] = 0.0f;
        else if (i < Nn * Hdim + Nn + Gg * Hdim) g_gsum[i - Nn * Hdim - Nn] = 0.0f;
        else g_gcnt[i - Nn * Hdim - Nn - Gg * Hdim] = 0.0f;
    }
}

// ---------------- P0: per-graph precompute + LN-fold vectors ----------------
__global__ __launch_bounds__(256, 1) void pu_kernel(
    const float* __restrict__ u, const float* __restrict__ eW1,
    const float* __restrict__ n2W1, const float* __restrict__ n2b1,
    const float* __restrict__ n1W1, const float* __restrict__ egm,
    const float* __restrict__ ebt) {
    __shared__ float su[4096], sw1[4096], sw2[4096];
    int tid = threadIdx.x;
    cp_smem<256>(su, u, 4096, tid);
    cp_smem<256>(sw1, eW1 + 192 * 64, 4096, tid);
    cp_smem<256>(sw2, n2W1 + 64 * 64, 4096, tid);
    __syncthreads();
    int g = tid >> 2, q = tid & 3;
#pragma unroll 4
    for (int jj = 0; jj < 16; ++jj) {
        int j = q * 16 + jj;
        float s1 = 0.0f, s2 = 0.0f;
#pragma unroll 4
        for (int k = 0; k < 64; ++k) {
            float uv = su[g * 64 + k];
            s1 += uv * sw1[k * 64 + j];
            s2 += uv * sw2[k * 64 + j];
        }
        g_PUe[g * 64 + j] = s1;
        g_PUn2[g * 64 + j] = s2 + n2b1[j];
    }
    if (tid < 64) {
        float s1 = 0.0f, s2 = 0.0f;
        for (int k = 0; k < 64; ++k) {
            float w = n1W1[(64 + k) * 64 + tid];
            s1 += egm[k] * w;
            s2 += ebt[k] * w;
        }
        g_LN1g[tid] = s1;
        g_LN1c[tid] = s2;
    }
}

// ---------------- P1: per-node precompute (persistent) ----------------
#define P_OWA 0
#define P_OWB 4096
#define P_OWQ 8192
#define P_OBp 12288
#define P_OX  12416
#define P_SBT 16768
#define P_SMEM_BYTES (16832 * 4)

__global__ __launch_bounds__(256, 2) void node_pre_kernel(
    const float* __restrict__ x, const int* __restrict__ batch,
    const float* __restrict__ eW1, const float* __restrict__ eb1,
    const float* __restrict__ nW1, const float* __restrict__ nb1) {
    extern __shared__ float sm[];
    int tid = threadIdx.x;
    cp_smem<256>(sm + P_OWA, eW1, 4096, tid);
    cp_smem<256>(sm + P_OWB, eW1 + 4096, 4096, tid);
    cp_smem<256>(sm + P_OWQ, nW1, 4096, tid);
    if (tid < 64) { sm[P_OBp + tid] = eb1[tid]; sm[P_OBp + 64 + tid] = nb1[tid]; }
    __syncthreads();
    const int i4 = (tid >> 4) << 2, j4 = (tid & 15) << 2;
    int* sbt = (int*)(sm + P_SBT);
    const int nTiles = (Nn + 63) / 64;
    for (int t = blockIdx.x; t < nTiles; t += gridDim.x) {
        {
            int e = tid >> 2, q = tid & 3;
            int n = t * 64 + e;
            bool valid = n < Nn;
            if (q == 0) sbt[e] = valid ? batch[n] : 0;
            float4* d = (float4*)(sm + P_OX + e * 68 + q * 16);
            const float4* s4 = (const float4*)(x + (size_t)n * 64 + q * 16);
#pragma unroll
            for (int i = 0; i < 4; ++i)
                d[i] = valid ? s4[i] : make_float4(0.f, 0.f, 0.f, 0.f);
        }
        __syncthreads();
        u64 acc[4][2];
        zero8(acc);
        gemmB2<64, 68>(sm + P_OX, sm + P_OWA, i4, j4, acc);
#pragma unroll
        for (int r = 0; r < 4; ++r) {
            int n2 = t * 64 + i4 + r;
            if (n2 < Nn) {
                int b = sbt[i4 + r];
                float4 pu = *(const float4*)(g_PUe + b * 64 + j4);
                float4 b1 = *(const float4*)(sm + P_OBp + j4);
                float2 p0 = unpack2(acc[r][0]); float2 p1 = unpack2(acc[r][1]);
                *(float4*)(g_P1p + (size_t)n2 * 64 + j4) =
                    make_float4(p0.x + pu.x + b1.x, p0.y + pu.y + b1.y, p1.x + pu.z + b1.z, p1.y + pu.w + b1.w);
            }
        }
        zero8(acc);
        gemmB2<64, 68>(sm + P_OX, sm + P_OWB, i4, j4, acc);
#pragma unroll
        for (int r = 0; r < 4; ++r) {
            int n2 = t * 64 + i4 + r;
            if (n2 < Nn) {
                float2 p0 = unpack2(acc[r][0]); float2 p1 = unpack2(acc[r][1]);
                *(float4*)(g_P2Q + (size_t)n2 * 128 + j4) = make_float4(p0.x, p0.y, p1.x, p1.y);
            }
        }
        zero8(acc);
        gemmB2<64, 68>(sm + P_OX, sm + P_OWQ, i4, j4, acc);
#pragma unroll
        for (int r = 0; r < 4; ++r) {
            int n2 = t * 64 + i4 + r;
            if (n2 < Nn) {
                float4 b1 = *(const float4*)(sm + P_OBp + 64 + j4);
                float2 p0 = unpack2(acc[r][0]); float2 p1 = unpack2(acc[r][1]);
                *(float4*)(g_P2Q + (size_t)n2 * 128 + 64 + j4) =
                    make_float4(p0.x + b1.x, p0.y + b1.y, p1.x + b1.z, p1.y + b1.w);
            }
        }
        __syncthreads();
    }
}

// ---------------- kernel 1: fused edge+message, two independent 32-edge halves ----------------
#define E_WE1 0
#define E_WE2 4096
#define E_WN1 8192
#define E_WN2 12288
#define E_BS  16384
#define E_HB  16896
#define E_HSZ 4480
// per-half: B0 @ +0 (2176), B1 @ +2176, ST @ +4352 (64), IDX @ +4416 (64)
#define E_SMEM_BYTES ((16896 + 2 * E_HSZ) * 4)

__global__ __launch_bounds__(256, 2) void edge_node1_kernel(
    const int* __restrict__ ei, const float* __restrict__ ea,
    const float* __restrict__ eW1, const float* __restrict__ eW2,
    const float* __restrict__ n1W1, const float* __restrict__ n1W2,
    const float* __restrict__ eb2v, const float* __restrict__ egm,
    const float* __restrict__ ebt, const float* __restrict__ nb2v,
    const float* __restrict__ ngm, const float* __restrict__ nbt,
    float* __restrict__ edge_out) {
    extern __shared__ float sm[];
    int tid = threadIdx.x;
    cp_smem<256>(sm + E_WE1, eW1 + 8192, 4096, tid);   // eW1c
    cp_smem<256>(sm + E_WE2, eW2, 4096, tid);
    for (int i = tid; i < 4096; i += 256)
        sm[E_WN1 + i] = n1W1[4096 + i] * egm[i >> 6];  // diag(egm) * n1W1b
    cp_smem<256>(sm + E_WN2, n1W2, 4096, tid);
    if (tid < 64) {
        sm[E_BS + tid] = eb2v[tid];        sm[E_BS + 64 + tid] = egm[tid];
        sm[E_BS + 128 + tid] = ebt[tid];   sm[E_BS + 192 + tid] = nb2v[tid];
        sm[E_BS + 256 + tid] = ngm[tid];   sm[E_BS + 320 + tid] = nbt[tid];
        sm[E_BS + 384 + tid] = g_LN1g[tid]; sm[E_BS + 448 + tid] = g_LN1c[tid];
    }
    __syncthreads();

    const int hf = tid >> 7;          // half id 0/1
    const int h = tid & 127;          // thread within half
    const int bar = hf + 1;           // named barrier id
    const int i4 = (h >> 4) << 2;     // 8 groups * 4 rows = 32 edges
    const int j4 = (h & 15) << 2;     // 16 groups * 4 cols

    float* B0 = sm + E_HB + hf * E_HSZ;
    float* B1 = B0 + 2176;
    float* ST = B0 + 4352;
    int* sidx = (int*)(B0 + 4416);

    const int nT = Ee / 32;  // 31250
    for (int t = blockIdx.x * 2 + hf; t < nT; t += gridDim.x * 2) {
        const int eg0 = t * 32;
        // S0: indices + ea gather
        if (h < 32) {
            int eg = eg0 + h;
            int r = ei[eg], c = ei[Ee + eg];
            sidx[h] = r; sidx[32 + h] = c;
            atomicAdd(&g_aggcnt[r], 1.0f);
        }
        {
            int e = h >> 2, q = h & 3;
            const float4* s4 = (const float4*)(ea + (size_t)(eg0 + e) * 64 + q * 16);
            float4* d = (float4*)(B0 + e * 68 + q * 16);
            d[0] = s4[0]; d[1] = s4[1]; d[2] = s4[2]; d[3] = s4[3];
        }
        HBAR(bar);
        // offsets + edge layer 1
        float4 off1[4], off2[4];
#pragma unroll
        for (int r = 0; r < 4; ++r) {
            int row = sidx[i4 + r], col = sidx[32 + i4 + r];
            float4 a1 = *(const float4*)(g_P1p + (size_t)row * 64 + j4);
            float4 a2 = *(const float4*)(g_P2Q + (size_t)col * 128 + j4);
            off1[r] = make_float4(a1.x + a2.x, a1.y + a2.y, a1.z + a2.z, a1.w + a2.w);
            off2[r] = *(const float4*)(g_P2Q + (size_t)col * 128 + 64 + j4);
        }
        u64 acc[4][2];
        zero8(acc);
        gemmB2<64, 68>(B0, sm + E_WE1, i4, j4, acc);
        HBAR(bar);                         // B0 reads done
        storeH2off(B0, i4, j4, acc, off1); // B0 := h1
        HBAR(bar);
        // edge layer 2 -> B1
        zero8(acc);
        gemmB2<64, 68>(B0, sm + E_WE2, i4, j4, acc);
        storeH2(B1, i4, j4, acc, sm + E_BS + 0);
        HBAR(bar);
        ln_stats32(B1, ST, h);
        HBAR(bar);
        // edge_out + msg layer 1 (LN folded): reads B1, writes B0
        {
            int j = h & 63, g2 = h >> 6;
            float gj = sm[E_BS + 64 + j], bj = sm[E_BS + 128 + j];
            float* eb = edge_out + (size_t)t * 2048;
#pragma unroll
            for (int r = 0; r < 16; ++r) {
                int e = g2 * 16 + r;
                float v = B1[e * 68 + j];
                eb[(size_t)e * 64 + j] = (v - ST[e]) * ST[32 + e] * gj + bj;
            }
        }
        zero8(acc);
        gemmB2<64, 68>(B1, sm + E_WN1, i4, j4, acc);
        {
            float4 gv4 = *(const float4*)(sm + E_BS + 384 + j4);
            float4 cv4 = *(const float4*)(sm + E_BS + 448 + j4);
#pragma unroll
            for (int r = 0; r < 4; ++r) {
                float m = ST[i4 + r], rs = ST[32 + i4 + r];
                float rm = rs * m;
                float2 p0 = unpack2(acc[r][0]); float2 p1 = unpack2(acc[r][1]);
                float* row = B0 + (i4 + r) * 68 + j4;
                row[0] = gelu_f(rs * p0.x - rm * gv4.x + cv4.x + off2[r].x);
                row[1] = gelu_f(rs * p0.y - rm * gv4.y + cv4.y + off2[r].y);
                row[2] = gelu_f(rs * p1.x - rm * gv4.z + cv4.z + off2[r].z);
                row[3] = gelu_f(rs * p1.y - rm * gv4.w + cv4.w + off2[r].w);
            }
        }
        HBAR(bar);
        // msg layer 2 -> B1
        zero8(acc);
        gemmB2<64, 68>(B0, sm + E_WN2, i4, j4, acc);
        storeH2(B1, i4, j4, acc, sm + E_BS + 192);
        HBAR(bar);
        ln_stats32(B1, ST, h);
        HBAR(bar);
        // scatter
        {
            float4 g4 = *(const float4*)(sm + E_BS + 256 + j4);
            float4 b4 = *(const float4*)(sm + E_BS + 320 + j4);
#pragma unroll
            for (int ebk = 0; ebk < 4; ++ebk) {
                int e = (h >> 4) + (ebk << 3);
                float mn = ST[e], rs = ST[32 + e];
                float4 v = *(const float4*)(B1 + e * 68 + j4);
                v.x = (v.x - mn) * rs * g4.x + b4.x;
                v.y = (v.y - mn) * rs * g4.y + b4.y;
                v.z = (v.z - mn) * rs * g4.z + b4.z;
                v.w = (v.w - mn) * rs * g4.w + b4.w;
                red_v4(g_aggsum + (size_t)sidx[e] * 64 + j4, v);
            }
        }
        HBAR(bar);
    }
}

// ---------------- kernel 2: node update (persistent) ----------------
#define N_OW1 0
#define N_OW2 4096
#define N_OB  8192
#define N_OX  8384
#define N_OH  12736
#define N_OST 17088
#define N_OBI 17216
#define N_SMEM_BYTES (17280 * 4)

__global__ __launch_bounds__(256, 2) void node2_kernel(
    const int* __restrict__ batch,
    const float* __restrict__ W1, const float* __restrict__ W2,
    const float* __restrict__ b2, const float* __restrict__ gm, const float* __restrict__ bt,
    float* __restrict__ x_out) {
    extern __shared__ float sm[];
    int tid = threadIdx.x;
    cp_smem<256>(sm + N_OW1, W1, 4096, tid);
    cp_smem<256>(sm + N_OW2, W2, 4096, tid);
    if (tid < 64) {
        sm[N_OB + tid] = b2[tid]; sm[N_OB + 64 + tid] = gm[tid]; sm[N_OB + 128 + tid] = bt[tid];
    }
    __syncthreads();
    const int i4 = (tid >> 4) << 2, j4 = (tid & 15) << 2;
    int* sbi = (int*)(sm + N_OBI);
    const int nTiles = (Nn + 63) / 64;
    for (int t = blockIdx.x; t < nTiles; t += gridDim.x) {
        {
            int e = tid >> 2, q = tid & 3;
            int n = t * 64 + e;
            bool valid = n < Nn;
            if (q == 0) {
                int b = valid ? batch[n] : 0;
                sbi[e] = b;
                if (valid) atomicAdd(&g_gcnt[b], 1.0f);
            }
            float inv = valid ? 1.0f / fmaxf(g_aggcnt[n], 1.0f) : 1.0f;
            float4* d = (float4*)(sm + N_OX + e * 68 + q * 16);
            const float4* s4 = (const float4*)(g_aggsum + (size_t)n * 64 + q * 16);
#pragma unroll
            for (int i = 0; i < 4; ++i) {
                float4 v = valid ? s4[i] : make_float4(0.f, 0.f, 0.f, 0.f);
                v.x *= inv; v.y *= inv; v.z *= inv; v.w *= inv;
                d[i] = v;
            }
        }
        __syncthreads();
        float4 off[4];
#pragma unroll
        for (int r = 0; r < 4; ++r) {
            int n2 = t * 64 + i4 + r;
            off[r] = make_float4(0.f, 0.f, 0.f, 0.f);
            if (n2 < Nn) off[r] = *(const float4*)(g_PUn2 + sbi[i4 + r] * 64 + j4);
        }
        u64 acc[4][2];
        zero8(acc);
        gemmB2<64, 68>(sm + N_OX, sm + N_OW1, i4, j4, acc);
        storeH2off(sm + N_OH, i4, j4, acc, off);
        __syncthreads();
        zero8(acc);
        gemmB2<64, 68>(sm + N_OH, sm + N_OW2, i4, j4, acc);
        __syncthreads();
        storeH2(sm + N_OH, i4, j4, acc, sm + N_OB);
        __syncthreads();
        ln_stats(sm + N_OH, sm + N_OST, tid);
        __syncthreads();
        {
            int j = tid & 63, g2 = tid >> 6;
            float gj = sm[N_OB + 64 + j], bj = sm[N_OB + 128 + j];
#pragma unroll
            for (int r = 0; r < 16; ++r) {
                int e = g2 * 16 + r;
                int n = t * 64 + e;
                float v = sm[N_OH + e * 68 + j];
                float nv = (v - sm[N_OST + e]) * sm[N_OST + 64 + e] * gj + bj;
                sm[N_OH + e * 68 + j] = nv;
                if (n < Nn) x_out[(size_t)n * 64 + j] = nv;
            }
        }
        __syncthreads();
        {
#pragma unroll
            for (int ebk = 0; ebk < 4; ++ebk) {
                int e = (tid >> 4) + (ebk << 4);
                int n = t * 64 + e;
                if (n < Nn) {
                    float4 v = *(const float4*)(sm + N_OH + e * 68 + j4);
                    red_v4(g_gsum + (size_t)sbi[e] * 64 + j4, v);
                }
            }
        }
        __syncthreads();
    }
}

// ---------------- kernel 3: global MLP ----------------
#define G_OW1 0
#define G_OW2 8192
#define G_OB  12288
#define G_OX  12544
#define G_OH  21056
#define G_OST 25408
#define G_SMEM_BYTES (25536 * 4)

__global__ __launch_bounds__(256, 1) void glob_kernel(
    const float* __restrict__ u,
    const float* __restrict__ W1, const float* __restrict__ b1,
    const float* __restrict__ W2, const float* __restrict__ b2,
    const float* __restrict__ gm, const float* __restrict__ bt,
    float* __restrict__ u_out) {
    extern __shared__ float sm[];
    int tid = threadIdx.x;
    cp_smem<256>(sm + G_OW1, W1, 8192, tid);
    cp_smem<256>(sm + G_OW2, W2, 4096, tid);
    if (tid < 64) {
        sm[G_OB + tid] = b1[tid];       sm[G_OB + 64 + tid] = b2[tid];
        sm[G_OB + 128 + tid] = gm[tid]; sm[G_OB + 192 + tid] = bt[tid];
    }
    __syncthreads();
    const int i4 = (tid >> 4) << 2, j4 = (tid & 15) << 2;
    {
        int e = tid >> 2, q = tid & 3;
        float inv = 1.0f / fmaxf(g_gcnt[e], 1.0f);
        const float4* su = (const float4*)(u + (size_t)e * 64 + q * 16);
        const float4* sg = (const float4*)(g_gsum + (size_t)e * 64 + q * 16);
        float4* du = (float4*)(sm + G_OX + e * 132 + q * 16);
        float4* dg = (float4*)(sm + G_OX + e * 132 + 64 + q * 16);
#pragma unroll
        for (int i = 0; i < 4; ++i) du[i] = su[i];
#pragma unroll
        for (int i = 0; i < 4; ++i) {
            float4 v = sg[i];
            v.x *= inv; v.y *= inv; v.z *= inv; v.w *= inv;
            dg[i] = v;
        }
    }
    __syncthreads();
    u64 acc[4][2];
    zero8(acc);
    gemmB2<128, 132>(sm + G_OX, sm + G_OW1, i4, j4, acc);
    storeH2(sm + G_OH, i4, j4, acc, sm + G_OB);
    __syncthreads();
    zero8(acc);
    gemmB2<64, 68>(sm + G_OH, sm + G_OW2, i4, j4, acc);
    __syncthreads();
    storeH2(sm + G_OH, i4, j4, acc, sm + G_OB + 64);
    __syncthreads();
    ln_stats(sm + G_OH, sm + G_OST, tid);
    __syncthreads();
    {
        int j = tid & 63, g2 = tid >> 6;
        float gj = sm[G_OB + 128 + j], bj = sm[G_OB + 192 + j];
#pragma unroll
        for (int r = 0; r < 16; ++r) {
            int e = g2 * 16 + r;
            float v = sm[G_OH + e * 68 + j];
            float nv = (v - sm[G_OST + e]) * sm[G_OST + 64 + e] * gj + bj;
            u_out[(size_t)e * 64 + j] = nv;
        }
    }
}

// ---------------- launch ----------------
extern "C" void kernel_launch(void* const* d_in, const int* in_sizes, int n_in,
                              void* d_out, int out_size) {
    const float* x = (const float*)d_in[0];
    const int* ei = (const int*)d_in[1];
    const float* ea = (const float*)d_in[2];
    const float* u = (const float*)d_in[3];
    const int* batch = (const int*)d_in[4];
    const float* eW1 = (const float*)d_in[5];
    const float* eb1 = (const float*)d_in[6];
    const float* eW2 = (const float*)d_in[7];
    const float* eb2 = (const float*)d_in[8];
    const float* egm = (const float*)d_in[9];
    const float* ebt = (const float*)d_in[10];
    const float* n1W1 = (const float*)d_in[11];
    const float* n1b1 = (const float*)d_in[12];
    const float* n1W2 = (const float*)d_in[13];
    const float* n1b2 = (const float*)d_in[14];
    const float* n1g = (const float*)d_in[15];
    const float* n1bt = (const float*)d_in[16];
    const float* n2W1 = (const float*)d_in[17];
    const float* n2b1 = (const float*)d_in[18];
    const float* n2W2 = (const float*)d_in[19];
    const float* n2b2 = (const float*)d_in[20];
    const float* n2g = (const float*)d_in[21];
    const float* n2bt = (const float*)d_in[22];
    const float* gW1 = (const float*)d_in[23];
    const float* gb1 = (const float*)d_in[24];
    const float* gW2 = (const float*)d_in[25];
    const float* gb2 = (const float*)d_in[26];
    const float* gg = (const float*)d_in[27];
    const float* gbt = (const float*)d_in[28];

    float* out = (float*)d_out;
    float* x_out = out;
    float* e_out = out + (size_t)Nn * 64;
    float* u_out = out + (size_t)(Nn + Ee) * 64;

    cudaFuncSetAttribute(node_pre_kernel, cudaFuncAttributeMaxDynamicSharedMemorySize, P_SMEM_BYTES);
    cudaFuncSetAttribute(edge_node1_kernel, cudaFuncAttributeMaxDynamicSharedMemorySize, E_SMEM_BYTES);
    cudaFuncSetAttribute(node2_kernel, cudaFuncAttributeMaxDynamicSharedMemorySize, N_SMEM_BYTES);
    cudaFuncSetAttribute(glob_kernel, cudaFuncAttributeMaxDynamicSharedMemorySize, G_SMEM_BYTES);

    zero_kernel<<<2048, 256>>>();
    pu_kernel<<<1, 256>>>(u, eW1, n2W1, n2b1, n1W1, egm, ebt);
    node_pre_kernel<<<296, 256, P_SMEM_BYTES>>>(x, batch, eW1, eb1, n1W1, n1b1);
    edge_node1_kernel<<<592, 256, E_SMEM_BYTES>>>(
        ei, ea, eW1, eW2, n1W1, n1W2,
        eb2, egm, ebt, n1b2, n1g, n1bt, e_out);
    node2_kernel<<<296, 256, N_SMEM_BYTES>>>(
        batch, n2W1, n2W2, n2b2, n2g, n2bt, x_out);
    glob_kernel<<<1, 256, G_SMEM_BYTES>>>(
        u, gW1, gb1, gW2, gb2, gg, gbt, u_out);
}